// round 6
// baseline (speedup 1.0000x reference)
#include <cuda_runtime.h>
#include <cuda_bf16.h>
#include <math_constants.h>

// Problem constants (fixed by setup_inputs)
#define NPTS  16384
#define BATCH 8
#define M     2048
#define CH    128

#define CAP       3072               // per-batch bucket capacity (mean 2048, sd ~42)
#define CHUNK_PTS 32                 // points per block (8 warps x 4 points)
#define NCHUNKS   (CAP / CHUNK_PTS)  // 96
#define FULL 0xffffffffu

typedef unsigned long long ull;

// Device scratch (no allocs allowed)
__device__ float  g_featsT[BATCH * M * CH];   // (B, m, C)
__device__ float4 g_known4[BATCH * M];        // coords padded to float4
__device__ int    g_bucket[BATCH * CAP];      // point ids grouped by batch
__device__ int    g_cnt[BATCH];               // per-batch counts

// ---------------------------------------------------------------------------
// Fused: feats transpose (B,C,m)->(B,m,C), TWO 32x32 XOR-swizzled tiles per
// block (64-wide m tile, MLP=2 on the global loads)      [z = 0..7]
//      + coord float4 pack / counter zero                [z = 8]
// Block: 256 threads flat.
// ---------------------------------------------------------------------------
__global__ void __launch_bounds__(256)
transpose_prep_kernel(const float* __restrict__ feats,
                      const float* __restrict__ known)
{
    const int t = threadIdx.x;
    if (blockIdx.z < BATCH) {
        // element (c,j) of each tile at tile[c*8 + ((j>>2) ^ ((c>>2)&7))].comp(j&3)
        __shared__ float4 tileA[32 * 8];
        __shared__ float4 tileB[32 * 8];
        const int b  = blockIdx.z;
        const int j0 = blockIdx.x * 64;       // m tile (two 32-wide halves)
        const int c0 = blockIdx.y * 32;       // channel tile

        {   // load: thread t -> channel c = t>>3, float4-chunk m4 = t&7
            const int c  = t >> 3;
            const int m4 = t & 7;
            const float* rowp = &feats[((size_t)(b * CH + c0 + c)) * M + j0];
            const float4 vA = *(const float4*)&rowp[m4 * 4];
            const float4 vB = *(const float4*)&rowp[32 + m4 * 4];
            const int sw = c * 8 + (m4 ^ ((c >> 2) & 7));
            tileA[sw] = vA;
            tileB[sw] = vB;
        }
        __syncthreads();
        {   // store: thread t -> m row j = t>>3, channel-chunk q = t&7
            const int j = t >> 3;
            const int q = t & 7;
            const int col4 = j >> 2;
            const int comp = j & 3;
            const float* tfA = (const float*)tileA;
            const float* tfB = (const float*)tileB;
            float vA[4], vB[4];
            #pragma unroll
            for (int i = 0; i < 4; i++) {
                const int c = 4 * q + i;
                const int off = c * 32 + ((col4 ^ ((c >> 2) & 7)) * 4) + comp;
                vA[i] = tfA[off];
                vB[i] = tfB[off];
            }
            *(float4*)&g_featsT[((size_t)(b * M + j0 + j)) * CH + c0 + 4 * q] =
                make_float4(vA[0], vA[1], vA[2], vA[3]);
            *(float4*)&g_featsT[((size_t)(b * M + j0 + 32 + j)) * CH + c0 + 4 * q] =
                make_float4(vB[0], vB[1], vB[2], vB[3]);
        }
    } else {
        const int i = (blockIdx.x * gridDim.y + blockIdx.y) * 256 + t;  // 0..32767
        if (i < BATCH) g_cnt[i] = 0;
        if (i < BATCH * M) {
            const float x = known[3 * i + 0];
            const float y = known[3 * i + 1];
            const float z = known[3 * i + 2];
            g_known4[i] = make_float4(x, y, z, 0.0f);
        }
    }
}

// ---------------------------------------------------------------------------
// Bucket points by batch. Bucket ORDER is nondeterministic (atomics) but the
// output is invariant to it: each point's result depends only on its own data.
// ---------------------------------------------------------------------------
__global__ void bucket_kernel(const int* __restrict__ batch_inds)
{
    __shared__ int hist[BATCH];
    __shared__ int base[BATCH];
    __shared__ int loc[BATCH];
    const int t = threadIdx.x;
    if (t < BATCH) { hist[t] = 0; loc[t] = 0; }
    __syncthreads();

    const int p = blockIdx.x * blockDim.x + t;
    const int b = batch_inds[p];
    atomicAdd(&hist[b], 1);
    __syncthreads();

    if (t < BATCH) base[t] = atomicAdd(&g_cnt[t], hist[t]);
    __syncthreads();

    const int r   = atomicAdd(&loc[b], 1);
    const int pos = base[b] + r;
    if (pos < CAP) g_bucket[b * CAP + pos] = p;
}

// ---------------------------------------------------------------------------
// Warp-collective top-3 update, called only on triggering batches (warp-
// uniform entry). Keys are (d_bits << 32 | idx): uint order of non-negative
// floats is monotone, ties resolve to the lower index (jax top_k semantics).
// k0<=k1<=k2 are replicated across the warp.
// ---------------------------------------------------------------------------
__device__ __forceinline__ void topk_update(bool pass, float d, int base, int lane,
                                            ull& k0, ull& k1, ull& k2)
{
    unsigned cur = pass ? __float_as_uint(d) : 0xFFFFFFFFu;
    while (true) {
        const unsigned mind   = __reduce_min_sync(FULL, cur);
        const unsigned owners = __ballot_sync(FULL, cur == mind);
        const int      src    = __ffs(owners) - 1;      // lowest lane = lowest idx
        const ull      mkey   = ((ull)mind << 32) | (unsigned)(base + src);
        if (mkey >= k2) break;
        const bool b0 = mkey < k0, b1 = mkey < k1;
        k2 = b1 ? k1 : mkey;
        k1 = b0 ? k0 : (b1 ? mkey : k1);
        k0 = b0 ? mkey : k0;
        if (lane == src) cur = 0xFFFFFFFFu;             // consume winner
        if (!__any_sync(FULL, cur <= (unsigned)(k2 >> 32))) break;  // cheap pre-break
    }
}

// Weights + feature gather + output write for one finished point.
__device__ __forceinline__ void write_point(int pid, int b, ull k0, ull k1, ull k2,
                                            int lane, float* __restrict__ out)
{
    const float d0 = __uint_as_float((unsigned)(k0 >> 32));
    const float d1 = __uint_as_float((unsigned)(k1 >> 32));
    const float d2 = __uint_as_float((unsigned)(k2 >> 32));
    float w0 = 1.0f / (sqrtf(d0) + 1e-8f);
    float w1 = 1.0f / (sqrtf(d1) + 1e-8f);
    float w2 = 1.0f / (sqrtf(d2) + 1e-8f);
    const float inv = 1.0f / (w0 + w1 + w2);
    w0 *= inv; w1 *= inv; w2 *= inv;

    const int i0 = (int)(unsigned)k0;
    const int i1 = (int)(unsigned)k1;
    const int i2 = (int)(unsigned)k2;

    const float4 a0 = ((const float4*)(g_featsT + ((size_t)(b * M + i0)) * CH))[lane];
    const float4 a1 = ((const float4*)(g_featsT + ((size_t)(b * M + i1)) * CH))[lane];
    const float4 a2 = ((const float4*)(g_featsT + ((size_t)(b * M + i2)) * CH))[lane];
    float4 o;
    o.x = fmaf(w0, a0.x, fmaf(w1, a1.x, w2 * a2.x));
    o.y = fmaf(w0, a0.y, fmaf(w1, a1.y, w2 * a2.y));
    o.z = fmaf(w0, a0.z, fmaf(w1, a1.z, w2 * a2.z));
    o.w = fmaf(w0, a0.w, fmaf(w1, a1.w, w2 * a2.w));
    ((float4*)out)[(size_t)pid * (CH / 4) + lane] = o;
}

// ---------------------------------------------------------------------------
// Main: block = (chunk of 32 points, batch). One batch's 2048 coords (float4)
// in 32KB smem. Each warp: 4 same-batch points. Fast path per 32-candidate
// batch: 4 distances + threshold tests + ONE combined warp vote; warp-
// collective top-3 updates only on triggering batches.
// ---------------------------------------------------------------------------
__global__ void __launch_bounds__(256)
knn_main_kernel(const float* __restrict__ unknown, float* __restrict__ out)
{
    __shared__ float4 sc[M];                      // 32 KB
    const int b     = blockIdx.y;
    const int cnt   = g_cnt[b];
    const int start = blockIdx.x * CHUNK_PTS;
    if (start >= cnt) return;                     // uniform exit, pre-sync

    const int t = threadIdx.x;
    {
        const float4* __restrict__ src4 = g_known4 + b * M;
        #pragma unroll
        for (int i = 0; i < M / 256; i++) sc[t + 256 * i] = src4[t + 256 * i];
    }
    __syncthreads();

    const int lane = t & 31;
    const int w    = t >> 5;

    int   pid[4];
    float ux[4], uy[4], uz[4], t2[4];
    ull   k0[4], k1[4], k2[4];
    #pragma unroll
    for (int k = 0; k < 4; k++) {
        const int ib = start + w * 4 + k;
        if (ib < cnt) {
            const int p = g_bucket[b * CAP + ib];
            pid[k] = p;
            ux[k] = unknown[p * 3 + 0];
            uy[k] = unknown[p * 3 + 1];
            uz[k] = unknown[p * 3 + 2];
            t2[k] = CUDART_INF_F;
        } else {
            pid[k] = -1;
            ux[k] = uy[k] = uz[k] = 0.0f;
            t2[k] = -CUDART_INF_F;                // never passes
        }
        k0[k] = k1[k] = k2[k] = ~0ull;
    }

    #pragma unroll 2
    for (int it = 0; it < M / 32; it++) {
        const int base = it * 32;
        const float4 c = sc[base + lane];

        float d[4]; bool p[4];
        #pragma unroll
        for (int k = 0; k < 4; k++) {
            const float dx = c.x - ux[k];
            const float dy = c.y - uy[k];
            const float dz = c.z - uz[k];
            d[k] = fmaf(dx, dx, fmaf(dy, dy, dz * dz));
            p[k] = d[k] <= t2[k];   // <= catches exact ties; key guard fixes index order
        }

        if (__any_sync(FULL, p[0] | p[1] | p[2] | p[3])) {
            #pragma unroll
            for (int k = 0; k < 4; k++) {
                if (__any_sync(FULL, p[k])) {
                    topk_update(p[k], d[k], base, lane, k0[k], k1[k], k2[k]);
                    t2[k] = __uint_as_float((unsigned)(k2[k] >> 32));
                }
            }
        }
    }

    #pragma unroll
    for (int k = 0; k < 4; k++)
        if (pid[k] >= 0) write_point(pid[k], b, k0[k], k1[k], k2[k], lane, out);
}

// ---------------------------------------------------------------------------
extern "C" void kernel_launch(void* const* d_in, const int* in_sizes, int n_in,
                              void* d_out, int out_size)
{
    const float* unknown     = (const float*)d_in[0];
    const float* known       = (const float*)d_in[1];
    const int*   batch_inds  = (const int*)d_in[2];
    const float* known_feats = (const float*)d_in[3];
    float* out = (float*)d_out;

    transpose_prep_kernel<<<dim3(M / 64, CH / 32, BATCH + 1), 256>>>(known_feats, known);
    bucket_kernel<<<NPTS / 256, 256>>>(batch_inds);
    knn_main_kernel<<<dim3(NCHUNKS, BATCH), 256>>>(unknown, out);
}

// round 7
// speedup vs baseline: 1.1145x; 1.1145x over previous
#include <cuda_runtime.h>
#include <cuda_bf16.h>
#include <math_constants.h>

// Problem constants (fixed by setup_inputs)
#define NPTS  16384
#define BATCH 8
#define M     2048
#define CH    128

#define CAP       3072               // per-batch bucket capacity (mean 2048, sd ~42)
#define CHUNK_PTS 16                 // points per block (8 warps x 2 points)
#define NCHUNKS   (CAP / CHUNK_PTS)  // 192
#define FULL 0xffffffffu

typedef unsigned long long ull;

// Device scratch (no allocs allowed)
__device__ float  g_featsT[BATCH * M * CH];   // (B, m, C)
__device__ float4 g_known4[BATCH * M];        // coords padded to float4
__device__ int    g_bucket[BATCH * CAP];      // point ids grouped by batch
__device__ int    g_cnt[BATCH];               // per-batch counts

// ---------------------------------------------------------------------------
// Fused: feats transpose (B,C,m)->(B,m,C), FOUR 32x32 XOR-swizzled tiles per
// block (128-wide m tile, MLP=4 on the global loads)     [z = 0..7]
//      + coord float4 pack / counter zero                [z = 8]
// Block: 256 threads flat.
// ---------------------------------------------------------------------------
__global__ void __launch_bounds__(256)
transpose_prep_kernel(const float* __restrict__ feats,
                      const float* __restrict__ known)
{
    const int t = threadIdx.x;
    if (blockIdx.z < BATCH) {
        // element (c,j) of tile q at tile[q][c*8 + ((j>>2) ^ ((c>>2)&7))].comp(j&3)
        __shared__ float4 tile[4][32 * 8];    // 16 KB
        const int b  = blockIdx.z;
        const int j0 = blockIdx.x * 128;      // m tile (four 32-wide quarters)
        const int c0 = blockIdx.y * 32;       // channel tile

        {   // load: thread t -> channel c = t>>3, float4-chunk m4 = t&7; 4 tiles
            const int c  = t >> 3;
            const int m4 = t & 7;
            const float* rowp = &feats[((size_t)(b * CH + c0 + c)) * M + j0];
            float4 v[4];
            #pragma unroll
            for (int q4 = 0; q4 < 4; q4++)            // 4 independent LDG.128
                v[q4] = *(const float4*)&rowp[q4 * 32 + m4 * 4];
            const int sw = c * 8 + (m4 ^ ((c >> 2) & 7));
            #pragma unroll
            for (int q4 = 0; q4 < 4; q4++)
                tile[q4][sw] = v[q4];
        }
        __syncthreads();
        {   // store: thread t -> m row j = t>>3, channel-chunk q = t&7; 4 tiles
            const int j = t >> 3;
            const int q = t & 7;
            const int col4 = j >> 2;
            const int comp = j & 3;
            #pragma unroll
            for (int q4 = 0; q4 < 4; q4++) {
                const float* tf = (const float*)tile[q4];
                float vv[4];
                #pragma unroll
                for (int i = 0; i < 4; i++) {
                    const int c = 4 * q + i;
                    vv[i] = tf[c * 32 + ((col4 ^ ((c >> 2) & 7)) * 4) + comp];
                }
                *(float4*)&g_featsT[((size_t)(b * M + j0 + q4 * 32 + j)) * CH + c0 + 4 * q] =
                    make_float4(vv[0], vv[1], vv[2], vv[3]);
            }
        }
    } else {
        const int i = (blockIdx.x * gridDim.y + blockIdx.y) * 256 + t;  // 0..16383
        if (i < BATCH) g_cnt[i] = 0;
        if (i < BATCH * M) {
            const float x = known[3 * i + 0];
            const float y = known[3 * i + 1];
            const float z = known[3 * i + 2];
            g_known4[i] = make_float4(x, y, z, 0.0f);
        }
    }
}

// ---------------------------------------------------------------------------
// Bucket points by batch. Bucket ORDER is nondeterministic (atomics) but the
// output is invariant to it: each point's result depends only on its own data.
// ---------------------------------------------------------------------------
__global__ void bucket_kernel(const int* __restrict__ batch_inds)
{
    __shared__ int hist[BATCH];
    __shared__ int base[BATCH];
    __shared__ int loc[BATCH];
    const int t = threadIdx.x;
    if (t < BATCH) { hist[t] = 0; loc[t] = 0; }
    __syncthreads();

    const int p = blockIdx.x * blockDim.x + t;
    const int b = batch_inds[p];
    atomicAdd(&hist[b], 1);
    __syncthreads();

    if (t < BATCH) base[t] = atomicAdd(&g_cnt[t], hist[t]);
    __syncthreads();

    const int r   = atomicAdd(&loc[b], 1);
    const int pos = base[b] + r;
    if (pos < CAP) g_bucket[b * CAP + pos] = p;
}

// ---------------------------------------------------------------------------
// Warp-collective top-3 update, called only on triggering batches (warp-
// uniform entry). Keys are (d_bits << 32 | idx): uint order of non-negative
// floats is monotone, ties resolve to the lower index (jax top_k semantics).
// k0<=k1<=k2 are replicated across the warp.
// ---------------------------------------------------------------------------
__device__ __forceinline__ void topk_update(bool pass, float d, int base, int lane,
                                            ull& k0, ull& k1, ull& k2)
{
    unsigned cur = pass ? __float_as_uint(d) : 0xFFFFFFFFu;
    while (true) {
        const unsigned mind   = __reduce_min_sync(FULL, cur);
        const unsigned owners = __ballot_sync(FULL, cur == mind);
        const int      src    = __ffs(owners) - 1;      // lowest lane = lowest idx
        const ull      mkey   = ((ull)mind << 32) | (unsigned)(base + src);
        if (mkey >= k2) break;
        const bool b0 = mkey < k0, b1 = mkey < k1;
        k2 = b1 ? k1 : mkey;
        k1 = b0 ? k0 : (b1 ? mkey : k1);
        k0 = b0 ? mkey : k0;
        if (lane == src) cur = 0xFFFFFFFFu;             // consume winner
        if (!__any_sync(FULL, cur <= (unsigned)(k2 >> 32))) break;  // cheap pre-break
    }
}

// Weights + feature gather + output write for one finished point.
__device__ __forceinline__ void write_point(int pid, int b, ull k0, ull k1, ull k2,
                                            int lane, float* __restrict__ out)
{
    const float d0 = __uint_as_float((unsigned)(k0 >> 32));
    const float d1 = __uint_as_float((unsigned)(k1 >> 32));
    const float d2 = __uint_as_float((unsigned)(k2 >> 32));
    float w0 = 1.0f / (sqrtf(d0) + 1e-8f);
    float w1 = 1.0f / (sqrtf(d1) + 1e-8f);
    float w2 = 1.0f / (sqrtf(d2) + 1e-8f);
    const float inv = 1.0f / (w0 + w1 + w2);
    w0 *= inv; w1 *= inv; w2 *= inv;

    const int i0 = (int)(unsigned)k0;
    const int i1 = (int)(unsigned)k1;
    const int i2 = (int)(unsigned)k2;

    const float4 a0 = ((const float4*)(g_featsT + ((size_t)(b * M + i0)) * CH))[lane];
    const float4 a1 = ((const float4*)(g_featsT + ((size_t)(b * M + i1)) * CH))[lane];
    const float4 a2 = ((const float4*)(g_featsT + ((size_t)(b * M + i2)) * CH))[lane];
    float4 o;
    o.x = fmaf(w0, a0.x, fmaf(w1, a1.x, w2 * a2.x));
    o.y = fmaf(w0, a0.y, fmaf(w1, a1.y, w2 * a2.y));
    o.z = fmaf(w0, a0.z, fmaf(w1, a1.z, w2 * a2.z));
    o.w = fmaf(w0, a0.w, fmaf(w1, a1.w, w2 * a2.w));
    ((float4*)out)[(size_t)pid * (CH / 4) + lane] = o;
}

// ---------------------------------------------------------------------------
// Main: block = (chunk of 16 points, batch). One batch's 2048 coords (float4)
// in 32KB smem. Each warp: 2 same-batch points. Fast path per 32-candidate
// batch: distances + threshold test + one warp vote; warp-collective top-3
// update only on triggering batches.
// ---------------------------------------------------------------------------
__global__ void __launch_bounds__(256)
knn_main_kernel(const float* __restrict__ unknown, float* __restrict__ out)
{
    __shared__ float4 sc[M];                      // 32 KB
    const int b     = blockIdx.y;
    const int cnt   = g_cnt[b];
    const int start = blockIdx.x * CHUNK_PTS;
    if (start >= cnt) return;                     // uniform exit, pre-sync

    const int t    = threadIdx.x;
    const int lane = t & 31;
    const int w    = t >> 5;

    // Issue point loads first so their latency overlaps the smem fill.
    int   pidA = -1, pidB = -1;
    float uxA = 0.f, uyA = 0.f, uzA = 0.f;
    float uxB = 0.f, uyB = 0.f, uzB = 0.f;
    float t2A = -CUDART_INF_F, t2B = -CUDART_INF_F;   // inactive -> never passes

    const int ibA = start + w * 2;
    const int ibB = ibA + 1;
    if (ibA < cnt) {
        pidA = g_bucket[b * CAP + ibA];
        uxA = unknown[pidA * 3 + 0];
        uyA = unknown[pidA * 3 + 1];
        uzA = unknown[pidA * 3 + 2];
        t2A = CUDART_INF_F;
    }
    if (ibB < cnt) {
        pidB = g_bucket[b * CAP + ibB];
        uxB = unknown[pidB * 3 + 0];
        uyB = unknown[pidB * 3 + 1];
        uzB = unknown[pidB * 3 + 2];
        t2B = CUDART_INF_F;
    }

    {
        const float4* __restrict__ src4 = g_known4 + b * M;
        #pragma unroll
        for (int i = 0; i < M / 256; i++) sc[t + 256 * i] = src4[t + 256 * i];
    }
    __syncthreads();

    ull k0A = ~0ull, k1A = ~0ull, k2A = ~0ull;
    ull k0B = ~0ull, k1B = ~0ull, k2B = ~0ull;

    #pragma unroll 2
    for (int it = 0; it < M / 32; it++) {
        const int base = it * 32;
        const float4 c = sc[base + lane];

        const float dxA = c.x - uxA, dyA = c.y - uyA, dzA = c.z - uzA;
        const float dA  = fmaf(dxA, dxA, fmaf(dyA, dyA, dzA * dzA));
        const float dxB = c.x - uxB, dyB = c.y - uyB, dzB = c.z - uzB;
        const float dB  = fmaf(dxB, dxB, fmaf(dyB, dyB, dzB * dzB));

        const bool pA = dA <= t2A;   // <= catches exact ties; key guard resolves index order
        const bool pB = dB <= t2B;
        if (__any_sync(FULL, pA || pB)) {
            if (__any_sync(FULL, pA)) {
                topk_update(pA, dA, base, lane, k0A, k1A, k2A);
                t2A = __uint_as_float((unsigned)(k2A >> 32));
            }
            if (__any_sync(FULL, pB)) {
                topk_update(pB, dB, base, lane, k0B, k1B, k2B);
                t2B = __uint_as_float((unsigned)(k2B >> 32));
            }
        }
    }

    if (pidA >= 0) write_point(pidA, b, k0A, k1A, k2A, lane, out);
    if (pidB >= 0) write_point(pidB, b, k0B, k1B, k2B, lane, out);
}

// ---------------------------------------------------------------------------
extern "C" void kernel_launch(void* const* d_in, const int* in_sizes, int n_in,
                              void* d_out, int out_size)
{
    const float* unknown     = (const float*)d_in[0];
    const float* known       = (const float*)d_in[1];
    const int*   batch_inds  = (const int*)d_in[2];
    const float* known_feats = (const float*)d_in[3];
    float* out = (float*)d_out;

    transpose_prep_kernel<<<dim3(M / 128, CH / 32, BATCH + 1), 256>>>(known_feats, known);
    bucket_kernel<<<NPTS / 256, 256>>>(batch_inds);
    knn_main_kernel<<<dim3(NCHUNKS, BATCH), 256>>>(unknown, out);
}

// round 8
// speedup vs baseline: 1.1348x; 1.0182x over previous
#include <cuda_runtime.h>
#include <cuda_bf16.h>
#include <math_constants.h>

// Problem constants (fixed by setup_inputs)
#define NPTS  16384
#define BATCH 8
#define M     2048
#define CH    128

#define CAP       3072               // per-batch bucket capacity (mean 2048, sd ~42)
#define CHUNK_PTS 16                 // points per block (8 warps x 2 points)
#define NCHUNKS   (CAP / CHUNK_PTS)  // 192
#define FULL 0xffffffffu

typedef unsigned long long ull;

// Device scratch (no allocs allowed)
__device__ float  g_featsT[BATCH * M * CH];   // (B, m, C)
__device__ float4 g_known4[BATCH * M];        // coords padded to float4
__device__ int    g_bucket[BATCH * CAP];      // point ids grouped by batch
__device__ int    g_cnt[BATCH];               // per-batch counts

// ---------------------------------------------------------------------------
// Fused: feats transpose (B,C,m)->(B,m,C), TWO 32x32 XOR-swizzled tiles per
// block (64-wide m tile, MLP=2 on the global loads)      [z = 0..7]
//      + coord float4 pack / counter zero                [z = 8]
// Block: 256 threads flat.  (Best measured transpose config: R6, 6.14us.)
// ---------------------------------------------------------------------------
__global__ void __launch_bounds__(256)
transpose_prep_kernel(const float* __restrict__ feats,
                      const float* __restrict__ known)
{
    const int t = threadIdx.x;
    if (blockIdx.z < BATCH) {
        // element (c,j) of each tile at tile[c*8 + ((j>>2) ^ ((c>>2)&7))].comp(j&3)
        __shared__ float4 tileA[32 * 8];
        __shared__ float4 tileB[32 * 8];
        const int b  = blockIdx.z;
        const int j0 = blockIdx.x * 64;       // m tile (two 32-wide halves)
        const int c0 = blockIdx.y * 32;       // channel tile

        {   // load: thread t -> channel c = t>>3, float4-chunk m4 = t&7
            const int c  = t >> 3;
            const int m4 = t & 7;
            const float* rowp = &feats[((size_t)(b * CH + c0 + c)) * M + j0];
            const float4 vA = *(const float4*)&rowp[m4 * 4];
            const float4 vB = *(const float4*)&rowp[32 + m4 * 4];
            const int sw = c * 8 + (m4 ^ ((c >> 2) & 7));
            tileA[sw] = vA;
            tileB[sw] = vB;
        }
        __syncthreads();
        {   // store: thread t -> m row j = t>>3, channel-chunk q = t&7
            const int j = t >> 3;
            const int q = t & 7;
            const int col4 = j >> 2;
            const int comp = j & 3;
            const float* tfA = (const float*)tileA;
            const float* tfB = (const float*)tileB;
            float vA[4], vB[4];
            #pragma unroll
            for (int i = 0; i < 4; i++) {
                const int c = 4 * q + i;
                const int off = c * 32 + ((col4 ^ ((c >> 2) & 7)) * 4) + comp;
                vA[i] = tfA[off];
                vB[i] = tfB[off];
            }
            *(float4*)&g_featsT[((size_t)(b * M + j0 + j)) * CH + c0 + 4 * q] =
                make_float4(vA[0], vA[1], vA[2], vA[3]);
            *(float4*)&g_featsT[((size_t)(b * M + j0 + 32 + j)) * CH + c0 + 4 * q] =
                make_float4(vB[0], vB[1], vB[2], vB[3]);
        }
    } else {
        const int i = (blockIdx.x * gridDim.y + blockIdx.y) * 256 + t;  // 0..32767
        if (i < BATCH) g_cnt[i] = 0;
        if (i < BATCH * M) {
            const float x = known[3 * i + 0];
            const float y = known[3 * i + 1];
            const float z = known[3 * i + 2];
            g_known4[i] = make_float4(x, y, z, 0.0f);
        }
    }
}

// ---------------------------------------------------------------------------
// Bucket points by batch. Bucket ORDER is nondeterministic (atomics) but the
// output is invariant to it: each point's result depends only on its own data.
// ---------------------------------------------------------------------------
__global__ void bucket_kernel(const int* __restrict__ batch_inds)
{
    __shared__ int hist[BATCH];
    __shared__ int base[BATCH];
    __shared__ int loc[BATCH];
    const int t = threadIdx.x;
    if (t < BATCH) { hist[t] = 0; loc[t] = 0; }
    __syncthreads();

    const int p = blockIdx.x * blockDim.x + t;
    const int b = batch_inds[p];
    atomicAdd(&hist[b], 1);
    __syncthreads();

    if (t < BATCH) base[t] = atomicAdd(&g_cnt[t], hist[t]);
    __syncthreads();

    const int r   = atomicAdd(&loc[b], 1);
    const int pos = base[b] + r;
    if (pos < CAP) g_bucket[b * CAP + pos] = p;
}

// ---------------------------------------------------------------------------
// Warp-collective top-3 update, called only on triggering windows (warp-
// uniform entry). Keys are (d_bits << 32 | idx): uint order of non-negative
// floats is monotone, ties resolve to the lower index (jax top_k semantics).
// k0<=k1<=k2 are replicated across the warp. Order-independent (set-min-3).
// ---------------------------------------------------------------------------
__device__ __forceinline__ void topk_update(bool pass, float d, int base, int lane,
                                            ull& k0, ull& k1, ull& k2)
{
    unsigned cur = pass ? __float_as_uint(d) : 0xFFFFFFFFu;
    while (true) {
        const unsigned mind   = __reduce_min_sync(FULL, cur);
        const unsigned owners = __ballot_sync(FULL, cur == mind);
        const int      src    = __ffs(owners) - 1;      // lowest lane = lowest idx
        const ull      mkey   = ((ull)mind << 32) | (unsigned)(base + src);
        if (mkey >= k2) break;
        const bool b0 = mkey < k0, b1 = mkey < k1;
        k2 = b1 ? k1 : mkey;
        k1 = b0 ? k0 : (b1 ? mkey : k1);
        k0 = b0 ? mkey : k0;
        if (lane == src) cur = 0xFFFFFFFFu;             // consume winner
        if (!__any_sync(FULL, cur <= (unsigned)(k2 >> 32))) break;  // cheap pre-break
    }
}

// Weights + feature gather + output write for one finished point.
__device__ __forceinline__ void write_point(int pid, int b, ull k0, ull k1, ull k2,
                                            int lane, float* __restrict__ out)
{
    const float d0 = __uint_as_float((unsigned)(k0 >> 32));
    const float d1 = __uint_as_float((unsigned)(k1 >> 32));
    const float d2 = __uint_as_float((unsigned)(k2 >> 32));
    float w0 = 1.0f / (sqrtf(d0) + 1e-8f);
    float w1 = 1.0f / (sqrtf(d1) + 1e-8f);
    float w2 = 1.0f / (sqrtf(d2) + 1e-8f);
    const float inv = 1.0f / (w0 + w1 + w2);
    w0 *= inv; w1 *= inv; w2 *= inv;

    const int i0 = (int)(unsigned)k0;
    const int i1 = (int)(unsigned)k1;
    const int i2 = (int)(unsigned)k2;

    const float4 a0 = ((const float4*)(g_featsT + ((size_t)(b * M + i0)) * CH))[lane];
    const float4 a1 = ((const float4*)(g_featsT + ((size_t)(b * M + i1)) * CH))[lane];
    const float4 a2 = ((const float4*)(g_featsT + ((size_t)(b * M + i2)) * CH))[lane];
    float4 o;
    o.x = fmaf(w0, a0.x, fmaf(w1, a1.x, w2 * a2.x));
    o.y = fmaf(w0, a0.y, fmaf(w1, a1.y, w2 * a2.y));
    o.z = fmaf(w0, a0.z, fmaf(w1, a1.z, w2 * a2.z));
    o.w = fmaf(w0, a0.w, fmaf(w1, a1.w, w2 * a2.w));
    ((float4*)out)[(size_t)pid * (CH / 4) + lane] = o;
}

// ---------------------------------------------------------------------------
// Main: block = (chunk of 16 points, batch). One batch's 2048 coords (float4)
// in 32KB smem. Each warp: 2 same-batch points, 2 candidates per lane per
// iteration (64-candidate vote window). Fast path: 2 LDS.128 + 4 distances +
// 4 threshold tests + ONE warp vote. Warp-collective top-3 updates only on
// triggering windows.
// ---------------------------------------------------------------------------
__global__ void __launch_bounds__(256)
knn_main_kernel(const float* __restrict__ unknown, float* __restrict__ out)
{
    __shared__ float4 sc[M];                      // 32 KB
    const int b     = blockIdx.y;
    const int cnt   = g_cnt[b];
    const int start = blockIdx.x * CHUNK_PTS;
    if (start >= cnt) return;                     // uniform exit, pre-sync

    const int t    = threadIdx.x;
    const int lane = t & 31;
    const int w    = t >> 5;

    // Issue point loads first so their latency overlaps the smem fill.
    int   pidA = -1, pidB = -1;
    float uxA = 0.f, uyA = 0.f, uzA = 0.f;
    float uxB = 0.f, uyB = 0.f, uzB = 0.f;
    float t2A = -CUDART_INF_F, t2B = -CUDART_INF_F;   // inactive -> never passes

    const int ibA = start + w * 2;
    const int ibB = ibA + 1;
    if (ibA < cnt) {
        pidA = g_bucket[b * CAP + ibA];
        uxA = unknown[pidA * 3 + 0];
        uyA = unknown[pidA * 3 + 1];
        uzA = unknown[pidA * 3 + 2];
        t2A = CUDART_INF_F;
    }
    if (ibB < cnt) {
        pidB = g_bucket[b * CAP + ibB];
        uxB = unknown[pidB * 3 + 0];
        uyB = unknown[pidB * 3 + 1];
        uzB = unknown[pidB * 3 + 2];
        t2B = CUDART_INF_F;
    }

    {
        const float4* __restrict__ src4 = g_known4 + b * M;
        #pragma unroll
        for (int i = 0; i < M / 256; i++) sc[t + 256 * i] = src4[t + 256 * i];
    }
    __syncthreads();

    ull k0A = ~0ull, k1A = ~0ull, k2A = ~0ull;
    ull k0B = ~0ull, k1B = ~0ull, k2B = ~0ull;

    #pragma unroll 2
    for (int it = 0; it < M / 64; it++) {
        const int base = it * 64;
        const float4 c1 = sc[base + lane];        // slice 1: idx base+lane
        const float4 c2 = sc[base + 32 + lane];   // slice 2: idx base+32+lane

        const float dxA1 = c1.x - uxA, dyA1 = c1.y - uyA, dzA1 = c1.z - uzA;
        const float dA1  = fmaf(dxA1, dxA1, fmaf(dyA1, dyA1, dzA1 * dzA1));
        const float dxA2 = c2.x - uxA, dyA2 = c2.y - uyA, dzA2 = c2.z - uzA;
        const float dA2  = fmaf(dxA2, dxA2, fmaf(dyA2, dyA2, dzA2 * dzA2));
        const float dxB1 = c1.x - uxB, dyB1 = c1.y - uyB, dzB1 = c1.z - uzB;
        const float dB1  = fmaf(dxB1, dxB1, fmaf(dyB1, dyB1, dzB1 * dzB1));
        const float dxB2 = c2.x - uxB, dyB2 = c2.y - uyB, dzB2 = c2.z - uzB;
        const float dB2  = fmaf(dxB2, dxB2, fmaf(dyB2, dyB2, dzB2 * dzB2));

        const bool pA1 = dA1 <= t2A, pA2 = dA2 <= t2A;
        const bool pB1 = dB1 <= t2B, pB2 = dB2 <= t2B;

        if (__any_sync(FULL, (pA1 | pA2) | (pB1 | pB2))) {
            if (__any_sync(FULL, pA1 | pA2)) {
                if (__any_sync(FULL, pA1)) topk_update(pA1, dA1, base,      lane, k0A, k1A, k2A);
                if (__any_sync(FULL, pA2)) topk_update(pA2, dA2, base + 32, lane, k0A, k1A, k2A);
                t2A = __uint_as_float((unsigned)(k2A >> 32));
            }
            if (__any_sync(FULL, pB1 | pB2)) {
                if (__any_sync(FULL, pB1)) topk_update(pB1, dB1, base,      lane, k0B, k1B, k2B);
                if (__any_sync(FULL, pB2)) topk_update(pB2, dB2, base + 32, lane, k0B, k1B, k2B);
                t2B = __uint_as_float((unsigned)(k2B >> 32));
            }
        }
    }

    if (pidA >= 0) write_point(pidA, b, k0A, k1A, k2A, lane, out);
    if (pidB >= 0) write_point(pidB, b, k0B, k1B, k2B, lane, out);
}

// ---------------------------------------------------------------------------
extern "C" void kernel_launch(void* const* d_in, const int* in_sizes, int n_in,
                              void* d_out, int out_size)
{
    const float* unknown     = (const float*)d_in[0];
    const float* known       = (const float*)d_in[1];
    const int*   batch_inds  = (const int*)d_in[2];
    const float* known_feats = (const float*)d_in[3];
    float* out = (float*)d_out;

    transpose_prep_kernel<<<dim3(M / 64, CH / 32, BATCH + 1), 256>>>(known_feats, known);
    bucket_kernel<<<NPTS / 256, 256>>>(batch_inds);
    knn_main_kernel<<<dim3(NCHUNKS, BATCH), 256>>>(unknown, out);
}

// round 9
// speedup vs baseline: 1.1747x; 1.0351x over previous
#include <cuda_runtime.h>
#include <cuda_bf16.h>
#include <math_constants.h>

// Problem constants (fixed by setup_inputs)
#define NPTS  16384
#define BATCH 8
#define M     2048
#define CH    128

#define CAP       3072               // per-batch bucket capacity (mean 2048, sd ~42)
#define CHUNK_PTS 16                 // points per block (8 warps x 2 points)
#define NCHUNKS   (CAP / CHUNK_PTS)  // 192
#define FULL 0xffffffffu

typedef unsigned long long ull;

// Device scratch (no allocs allowed)
__device__ float  g_featsT[BATCH * M * CH];   // (B, m, C)
__device__ float4 g_known4[BATCH * M];        // coords padded to float4
__device__ int    g_bucket[BATCH * CAP];      // point ids grouped by batch
__device__ int    g_cnt[BATCH];               // per-batch counts

// ---------------------------------------------------------------------------
// Fused: feats transpose (B,C,m)->(B,m,C), TWO 32x32 XOR-swizzled tiles per
// block (64-wide m tile, MLP=2 on the global loads)      [z = 0..7]
//      + coord float4 pack / counter zero                [z = 8]
// Block: 256 threads flat.  (Best measured transpose config: R6, 6.14us.)
// ---------------------------------------------------------------------------
__global__ void __launch_bounds__(256)
transpose_prep_kernel(const float* __restrict__ feats,
                      const float* __restrict__ known)
{
    const int t = threadIdx.x;
    if (blockIdx.z < BATCH) {
        // element (c,j) of each tile at tile[c*8 + ((j>>2) ^ ((c>>2)&7))].comp(j&3)
        __shared__ float4 tileA[32 * 8];
        __shared__ float4 tileB[32 * 8];
        const int b  = blockIdx.z;
        const int j0 = blockIdx.x * 64;       // m tile (two 32-wide halves)
        const int c0 = blockIdx.y * 32;       // channel tile

        {   // load: thread t -> channel c = t>>3, float4-chunk m4 = t&7
            const int c  = t >> 3;
            const int m4 = t & 7;
            const float* rowp = &feats[((size_t)(b * CH + c0 + c)) * M + j0];
            const float4 vA = *(const float4*)&rowp[m4 * 4];
            const float4 vB = *(const float4*)&rowp[32 + m4 * 4];
            const int sw = c * 8 + (m4 ^ ((c >> 2) & 7));
            tileA[sw] = vA;
            tileB[sw] = vB;
        }
        __syncthreads();
        {   // store: thread t -> m row j = t>>3, channel-chunk q = t&7
            const int j = t >> 3;
            const int q = t & 7;
            const int col4 = j >> 2;
            const int comp = j & 3;
            const float* tfA = (const float*)tileA;
            const float* tfB = (const float*)tileB;
            float vA[4], vB[4];
            #pragma unroll
            for (int i = 0; i < 4; i++) {
                const int c = 4 * q + i;
                const int off = c * 32 + ((col4 ^ ((c >> 2) & 7)) * 4) + comp;
                vA[i] = tfA[off];
                vB[i] = tfB[off];
            }
            *(float4*)&g_featsT[((size_t)(b * M + j0 + j)) * CH + c0 + 4 * q] =
                make_float4(vA[0], vA[1], vA[2], vA[3]);
            *(float4*)&g_featsT[((size_t)(b * M + j0 + 32 + j)) * CH + c0 + 4 * q] =
                make_float4(vB[0], vB[1], vB[2], vB[3]);
        }
    } else {
        const int i = (blockIdx.x * gridDim.y + blockIdx.y) * 256 + t;  // 0..32767
        if (i < BATCH) g_cnt[i] = 0;
        if (i < BATCH * M) {
            const float x = known[3 * i + 0];
            const float y = known[3 * i + 1];
            const float z = known[3 * i + 2];
            g_known4[i] = make_float4(x, y, z, 0.0f);
        }
    }
}

// ---------------------------------------------------------------------------
// Bucket points by batch. Bucket ORDER is nondeterministic (atomics) but the
// output is invariant to it: each point's result depends only on its own data.
// ---------------------------------------------------------------------------
__global__ void bucket_kernel(const int* __restrict__ batch_inds)
{
    __shared__ int hist[BATCH];
    __shared__ int base[BATCH];
    __shared__ int loc[BATCH];
    const int t = threadIdx.x;
    if (t < BATCH) { hist[t] = 0; loc[t] = 0; }
    __syncthreads();

    const int p = blockIdx.x * blockDim.x + t;
    const int b = batch_inds[p];
    atomicAdd(&hist[b], 1);
    __syncthreads();

    if (t < BATCH) base[t] = atomicAdd(&g_cnt[t], hist[t]);
    __syncthreads();

    const int r   = atomicAdd(&loc[b], 1);
    const int pos = base[b] + r;
    if (pos < CAP) g_bucket[b * CAP + pos] = p;
}

// ---------------------------------------------------------------------------
// Warp-collective top-3 update, called only on triggering windows (warp-
// uniform entry). Keys are (d_bits << 32 | idx): uint order of non-negative
// floats is monotone, ties resolve to the lower index (jax top_k semantics).
// k0<=k1<=k2 are replicated across the warp. Order-independent (set-min-3).
// ---------------------------------------------------------------------------
__device__ __forceinline__ void topk_update(bool pass, float d, int base, int lane,
                                            ull& k0, ull& k1, ull& k2)
{
    unsigned cur = pass ? __float_as_uint(d) : 0xFFFFFFFFu;
    while (true) {
        const unsigned mind   = __reduce_min_sync(FULL, cur);
        const unsigned owners = __ballot_sync(FULL, cur == mind);
        const int      src    = __ffs(owners) - 1;      // lowest lane = lowest idx
        const ull      mkey   = ((ull)mind << 32) | (unsigned)(base + src);
        if (mkey >= k2) break;
        const bool b0 = mkey < k0, b1 = mkey < k1;
        k2 = b1 ? k1 : mkey;
        k1 = b0 ? k0 : (b1 ? mkey : k1);
        k0 = b0 ? mkey : k0;
        if (lane == src) cur = 0xFFFFFFFFu;             // consume winner
        if (!__any_sync(FULL, cur <= (unsigned)(k2 >> 32))) break;  // cheap pre-break
    }
}

// Weights + feature gather + output write for one finished point.
__device__ __forceinline__ void write_point(int pid, int b, ull k0, ull k1, ull k2,
                                            int lane, float* __restrict__ out)
{
    const float d0 = __uint_as_float((unsigned)(k0 >> 32));
    const float d1 = __uint_as_float((unsigned)(k1 >> 32));
    const float d2 = __uint_as_float((unsigned)(k2 >> 32));
    float w0 = 1.0f / (sqrtf(d0) + 1e-8f);
    float w1 = 1.0f / (sqrtf(d1) + 1e-8f);
    float w2 = 1.0f / (sqrtf(d2) + 1e-8f);
    const float inv = 1.0f / (w0 + w1 + w2);
    w0 *= inv; w1 *= inv; w2 *= inv;

    const int i0 = (int)(unsigned)k0;
    const int i1 = (int)(unsigned)k1;
    const int i2 = (int)(unsigned)k2;

    const float4 a0 = ((const float4*)(g_featsT + ((size_t)(b * M + i0)) * CH))[lane];
    const float4 a1 = ((const float4*)(g_featsT + ((size_t)(b * M + i1)) * CH))[lane];
    const float4 a2 = ((const float4*)(g_featsT + ((size_t)(b * M + i2)) * CH))[lane];
    float4 o;
    o.x = fmaf(w0, a0.x, fmaf(w1, a1.x, w2 * a2.x));
    o.y = fmaf(w0, a0.y, fmaf(w1, a1.y, w2 * a2.y));
    o.z = fmaf(w0, a0.z, fmaf(w1, a1.z, w2 * a2.z));
    o.w = fmaf(w0, a0.w, fmaf(w1, a1.w, w2 * a2.w));
    ((float4*)out)[(size_t)pid * (CH / 4) + lane] = o;
}

// ---------------------------------------------------------------------------
// Main: block = (chunk of 16 points, batch). One batch's 2048 coords (float4)
// in 32KB smem. Each warp: 2 same-batch points, 2 candidates per lane per
// iteration (64-candidate vote window). Fast path: 2 LDS.128 + 4 distances +
// 4 threshold tests + ONE warp vote. Warp-collective top-3 updates only on
// triggering windows.
// ---------------------------------------------------------------------------
__global__ void __launch_bounds__(256)
knn_main_kernel(const float* __restrict__ unknown, float* __restrict__ out)
{
    __shared__ float4 sc[M];                      // 32 KB
    const int b     = blockIdx.y;
    const int cnt   = g_cnt[b];
    const int start = blockIdx.x * CHUNK_PTS;
    if (start >= cnt) return;                     // uniform exit, pre-sync

    const int t    = threadIdx.x;
    const int lane = t & 31;
    const int w    = t >> 5;

    // Issue point loads first so their latency overlaps the smem fill.
    int   pidA = -1, pidB = -1;
    float uxA = 0.f, uyA = 0.f, uzA = 0.f;
    float uxB = 0.f, uyB = 0.f, uzB = 0.f;
    float t2A = -CUDART_INF_F, t2B = -CUDART_INF_F;   // inactive -> never passes

    const int ibA = start + w * 2;
    const int ibB = ibA + 1;
    if (ibA < cnt) {
        pidA = g_bucket[b * CAP + ibA];
        uxA = unknown[pidA * 3 + 0];
        uyA = unknown[pidA * 3 + 1];
        uzA = unknown[pidA * 3 + 2];
        t2A = CUDART_INF_F;
    }
    if (ibB < cnt) {
        pidB = g_bucket[b * CAP + ibB];
        uxB = unknown[pidB * 3 + 0];
        uyB = unknown[pidB * 3 + 1];
        uzB = unknown[pidB * 3 + 2];
        t2B = CUDART_INF_F;
    }

    {
        const float4* __restrict__ src4 = g_known4 + b * M;
        #pragma unroll
        for (int i = 0; i < M / 256; i++) sc[t + 256 * i] = src4[t + 256 * i];
    }
    __syncthreads();

    ull k0A = ~0ull, k1A = ~0ull, k2A = ~0ull;
    ull k0B = ~0ull, k1B = ~0ull, k2B = ~0ull;

    #pragma unroll 2
    for (int it = 0; it < M / 64; it++) {
        const int base = it * 64;
        const float4 c1 = sc[base + lane];        // slice 1: idx base+lane
        const float4 c2 = sc[base + 32 + lane];   // slice 2: idx base+32+lane

        const float dxA1 = c1.x - uxA, dyA1 = c1.y - uyA, dzA1 = c1.z - uzA;
        const float dA1  = fmaf(dxA1, dxA1, fmaf(dyA1, dyA1, dzA1 * dzA1));
        const float dxA2 = c2.x - uxA, dyA2 = c2.y - uyA, dzA2 = c2.z - uzA;
        const float dA2  = fmaf(dxA2, dxA2, fmaf(dyA2, dyA2, dzA2 * dzA2));
        const float dxB1 = c1.x - uxB, dyB1 = c1.y - uyB, dzB1 = c1.z - uzB;
        const float dB1  = fmaf(dxB1, dxB1, fmaf(dyB1, dyB1, dzB1 * dzB1));
        const float dxB2 = c2.x - uxB, dyB2 = c2.y - uyB, dzB2 = c2.z - uzB;
        const float dB2  = fmaf(dxB2, dxB2, fmaf(dyB2, dyB2, dzB2 * dzB2));

        const bool pA1 = dA1 <= t2A, pA2 = dA2 <= t2A;
        const bool pB1 = dB1 <= t2B, pB2 = dB2 <= t2B;

        if (__any_sync(FULL, (pA1 | pA2) | (pB1 | pB2))) {
            if (__any_sync(FULL, pA1 | pA2)) {
                if (__any_sync(FULL, pA1)) topk_update(pA1, dA1, base,      lane, k0A, k1A, k2A);
                if (__any_sync(FULL, pA2)) topk_update(pA2, dA2, base + 32, lane, k0A, k1A, k2A);
                t2A = __uint_as_float((unsigned)(k2A >> 32));
            }
            if (__any_sync(FULL, pB1 | pB2)) {
                if (__any_sync(FULL, pB1)) topk_update(pB1, dB1, base,      lane, k0B, k1B, k2B);
                if (__any_sync(FULL, pB2)) topk_update(pB2, dB2, base + 32, lane, k0B, k1B, k2B);
                t2B = __uint_as_float((unsigned)(k2B >> 32));
            }
        }
    }

    if (pidA >= 0) write_point(pidA, b, k0A, k1A, k2A, lane, out);
    if (pidB >= 0) write_point(pidB, b, k0B, k1B, k2B, lane, out);
}

// ---------------------------------------------------------------------------
extern "C" void kernel_launch(void* const* d_in, const int* in_sizes, int n_in,
                              void* d_out, int out_size)
{
    const float* unknown     = (const float*)d_in[0];
    const float* known       = (const float*)d_in[1];
    const int*   batch_inds  = (const int*)d_in[2];
    const float* known_feats = (const float*)d_in[3];
    float* out = (float*)d_out;

    transpose_prep_kernel<<<dim3(M / 64, CH / 32, BATCH + 1), 256>>>(known_feats, known);
    bucket_kernel<<<NPTS / 256, 256>>>(batch_inds);
    knn_main_kernel<<<dim3(NCHUNKS, BATCH), 256>>>(unknown, out);
}